// round 13
// baseline (speedup 1.0000x reference)
#include <cuda_runtime.h>
#include <cuda_bf16.h>
#include <cstdint>
#include <cstddef>

#define SEQ 2048
#define DIM 1024
#define NH 16
#define HD 64
#define ROWS 16
#define COLT 256
#define SCP 2052   // padded score-row pitch (floats): de-banks A-fragment reads

// Scratch (allocation-free rule: __device__ globals)
__device__ float g_Q[SEQ * DIM];
__device__ float g_K[SEQ * DIM];
__device__ float g_V[SEQ * DIM];

__device__ __nv_bfloat16 g_xh[SEQ * DIM], g_xm[SEQ * DIM];
__device__ __nv_bfloat16 g_aoh[SEQ * DIM], g_aom[SEQ * DIM];
__device__ __nv_bfloat16 g_wvh[DIM * DIM], g_wvm[DIM * DIM];
__device__ __nv_bfloat16 g_woh[DIM * DIM], g_wom[DIM * DIM];

// ===========================================================================
// Helpers
// ===========================================================================
__device__ __forceinline__ uint32_t smem_u32(const void* p) {
    uint32_t a;
    asm("{ .reg .u64 t; cvta.to.shared.u64 t, %1; cvt.u32.u64 %0, t; }"
        : "=r"(a) : "l"(p));
    return a;
}
__device__ __forceinline__ void ldsm4(uint32_t* r, uint32_t addr) {
    asm volatile("ldmatrix.sync.aligned.m8n8.x4.shared.b16 {%0,%1,%2,%3}, [%4];"
                 : "=r"(r[0]), "=r"(r[1]), "=r"(r[2]), "=r"(r[3]) : "r"(addr));
}
__device__ __forceinline__ void mma16816(float* c, const uint32_t* a, const uint32_t* b) {
    asm volatile(
        "mma.sync.aligned.m16n8k16.row.col.f32.bf16.bf16.f32 "
        "{%0,%1,%2,%3}, {%4,%5,%6,%7}, {%8,%9}, {%0,%1,%2,%3};"
        : "+f"(c[0]), "+f"(c[1]), "+f"(c[2]), "+f"(c[3])
        : "r"(a[0]), "r"(a[1]), "r"(a[2]), "r"(a[3]), "r"(b[0]), "r"(b[1]));
}
__device__ __forceinline__ void cp16(uint32_t s, const void* g) {
    asm volatile("cp.async.ca.shared.global [%0], [%1], 16;" :: "r"(s), "l"(g));
}
// pack float2 -> bf16x2 (hi half)
__device__ __forceinline__ uint32_t bf2h(float2 v) {
    __nv_bfloat162 b = __floats2bfloat162_rn(v.x, v.y);
    return *(uint32_t*)&b;
}
// residual (v - h) -> bf16x2
__device__ __forceinline__ uint32_t bf2m(float2 v, uint32_t hbits) {
    __nv_bfloat162 h = *(__nv_bfloat162*)&hbits;
    return bf2h(make_float2(v.x - __bfloat162float(h.x),
                            v.y - __bfloat162float(h.y)));
}

// ===========================================================================
// Split fp32 -> 2x bf16 (h + m captures ~16 mantissa bits)
// ===========================================================================
__global__ __launch_bounds__(256) void split2(
    const float* __restrict__ in, __nv_bfloat16* __restrict__ h,
    __nv_bfloat16* __restrict__ m, int n4)
{
    int i = blockIdx.x * 256 + threadIdx.x;
    if (i >= n4) return;
    float4 v = ((const float4*)in)[i];
    float f[4] = {v.x, v.y, v.z, v.w};
    __nv_bfloat16 hh[4], mm[4];
#pragma unroll
    for (int j = 0; j < 4; j++) {
        hh[j] = __float2bfloat16_rn(f[j]);
        mm[j] = __float2bfloat16_rn(f[j] - __bfloat162float(hh[j]));
    }
    ((__nv_bfloat162*)h)[i * 2 + 0] = __nv_bfloat162(hh[0], hh[1]);
    ((__nv_bfloat162*)h)[i * 2 + 1] = __nv_bfloat162(hh[2], hh[3]);
    ((__nv_bfloat162*)m)[i * 2 + 0] = __nv_bfloat162(mm[0], mm[1]);
    ((__nv_bfloat162*)m)[i * 2 + 1] = __nv_bfloat162(mm[2], mm[3]);
}

// ===========================================================================
// fp32 SIMT SGEMM (fp32-faithful; feeds the entmax-sensitive score path).
// Double-buffered SMEM. C[M,N] = A[M,K]*B[N,K]^T. blockIdx.z picks (B,C).
// ===========================================================================
__global__ __launch_bounds__(256, 2) void sgemm_nt3(
    const float* __restrict__ A,
    const float* __restrict__ B0, const float* __restrict__ B1, const float* __restrict__ B2,
    float* __restrict__ C0, float* __restrict__ C1, float* __restrict__ C2,
    int Kdim, int Ndim)
{
    const float* B = (blockIdx.z == 0) ? B0 : ((blockIdx.z == 1) ? B1 : B2);
    float* C = (blockIdx.z == 0) ? C0 : ((blockIdx.z == 1) ? C1 : C2);

    __shared__ __align__(16) float As[2][8][128];
    __shared__ __align__(16) float Bs[2][8][128];

    const int tid = threadIdx.x;
    const int m0 = blockIdx.y * 128;
    const int n0 = blockIdx.x * 128;
    const float* Ab = A + (size_t)m0 * Kdim;
    const float* Bb = B + (size_t)n0 * Kdim;

    const int lr = tid >> 1;
    const int lk = (tid & 1) * 4;

    const int warp = tid >> 5, lane = tid & 31;
    const int tr = (warp & 3) * 32 + (lane & 3) * 8;
    const int tc = (warp >> 2) * 64 + (lane >> 2) * 8;

    float acc[8][8];
#pragma unroll
    for (int i = 0; i < 8; i++)
#pragma unroll
        for (int j = 0; j < 8; j++) acc[i][j] = 0.f;

    const int NC = Kdim >> 3;
    for (int c = 0; c < NC; c++) {
        const int s = c & 1;
        const int k0 = c << 3;
        float4 a4 = *(const float4*)(Ab + (size_t)lr * Kdim + k0 + lk);
        float4 b4 = *(const float4*)(Bb + (size_t)lr * Kdim + k0 + lk);
        As[s][lk + 0][lr] = a4.x; As[s][lk + 1][lr] = a4.y;
        As[s][lk + 2][lr] = a4.z; As[s][lk + 3][lr] = a4.w;
        Bs[s][lk + 0][lr] = b4.x; Bs[s][lk + 1][lr] = b4.y;
        Bs[s][lk + 2][lr] = b4.z; Bs[s][lk + 3][lr] = b4.w;
        __syncthreads();
#pragma unroll
        for (int kk = 0; kk < 8; kk++) {
            float ar[8], br[8];
            *(float4*)(ar)     = *(const float4*)&As[s][kk][tr];
            *(float4*)(ar + 4) = *(const float4*)&As[s][kk][tr + 4];
            *(float4*)(br)     = *(const float4*)&Bs[s][kk][tc];
            *(float4*)(br + 4) = *(const float4*)&Bs[s][kk][tc + 4];
#pragma unroll
            for (int i = 0; i < 8; i++)
#pragma unroll
                for (int j = 0; j < 8; j++) acc[i][j] += ar[i] * br[j];
        }
    }

#pragma unroll
    for (int i = 0; i < 8; i++) {
        float* crow = C + (size_t)(m0 + tr + i) * Ndim + n0 + tc;
        *(float4*)(crow)     = make_float4(acc[i][0], acc[i][1], acc[i][2], acc[i][3]);
        *(float4*)(crow + 4) = make_float4(acc[i][4], acc[i][5], acc[i][6], acc[i][7]);
    }
}

// ===========================================================================
// bf16 3-term tensor-core GEMM: C = Ah*Bh + Am*Bh + Ah*Bm  (~2^-18 element)
// For entmax-insensitive paths only (V projection, Wo projection).
// ===========================================================================
#define GPITCH 80
#define GTILE  (128 * GPITCH)
#define GSTAGE (4 * GTILE)
#define GSMEM  (3 * GSTAGE)
#define S_AH 0
#define S_AM 1
#define S_BH 2
#define S_BM 3

__global__ __launch_bounds__(256) void gemm_bf3(
    const __nv_bfloat16* __restrict__ Ah, const __nv_bfloat16* __restrict__ Am,
    const __nv_bfloat16* __restrict__ Bh, const __nv_bfloat16* __restrict__ Bm,
    float* __restrict__ C, int Kdim, int Ndim)
{
    extern __shared__ __align__(16) char smem[];

    const int tid = threadIdx.x;
    const int lane = tid & 31, warp = tid >> 5;
    const int m0 = blockIdx.y * 128;
    const int n0 = blockIdx.x * 128;
    const int wm = (warp >> 2) * 64;
    const int wn = (warp & 3) * 32;
    const int lr = tid >> 2;
    const int lq = tid & 3;

    const uint32_t sb = smem_u32(smem);
    const uint32_t aBase = sb + (uint32_t)(wm + (lane & 15)) * GPITCH + (lane >> 4) * 16;
    const uint32_t bBase = sb + (uint32_t)(wn + ((lane >> 4) << 3) + (lane & 7)) * GPITCH
                              + ((lane >> 3) & 1) * 16;

    float acc[4][4][4];
#pragma unroll
    for (int a = 0; a < 4; a++)
#pragma unroll
        for (int b = 0; b < 4; b++)
#pragma unroll
            for (int k = 0; k < 4; k++) acc[a][b][k] = 0.f;

    const int NC = Kdim >> 5;

#define ISSUE_SUB(G, row0, sub, st, k0)                                         \
    {                                                                           \
        _Pragma("unroll")                                                       \
        for (int it = 0; it < 2; it++) {                                        \
            int r = lr + it * 64;                                               \
            cp16(sb + (st) * GSTAGE + (sub) * GTILE + r * GPITCH + lq * 16,     \
                 (const char*)(G) + ((size_t)((row0) + r) * Kdim + (k0)) * 2 + lq * 16); \
        }                                                                       \
    }
#define ISSUE(ch, st)                                                           \
    {                                                                           \
        const int k0_ = (ch) * 32;                                              \
        ISSUE_SUB(Ah, m0, S_AH, st, k0_);                                       \
        ISSUE_SUB(Am, m0, S_AM, st, k0_);                                       \
        ISSUE_SUB(Bh, n0, S_BH, st, k0_);                                       \
        ISSUE_SUB(Bm, n0, S_BM, st, k0_);                                       \
        asm volatile("cp.async.commit_group;");                                 \
    }

    ISSUE(0, 0);
    ISSUE(1, 1);

    for (int c = 0; c < NC; c++) {
        const int st = c % 3;
        if (c + 1 < NC) asm volatile("cp.async.wait_group 1;");
        else            asm volatile("cp.async.wait_group 0;");
        __syncthreads();
        if (c + 2 < NC) ISSUE(c + 2, (c + 2) % 3);

        const uint32_t sah = aBase + st * GSTAGE;
        const uint32_t sbh = bBase + st * GSTAGE + S_BH * GTILE;
#pragma unroll
        for (int ks = 0; ks < 2; ks++) {
            const uint32_t ko = ks * 32;
            uint32_t ah[4][4], am[4], bh[8], bm[8];
#pragma unroll
            for (int mb = 0; mb < 4; mb++)
                ldsm4(ah[mb], sah + S_AH * GTILE + mb * (16 * GPITCH) + ko);
            ldsm4(bh,     sbh + ko);
            ldsm4(bh + 4, sbh + 16 * GPITCH + ko);
#pragma unroll
            for (int mb = 0; mb < 4; mb++)
#pragma unroll
                for (int nb = 0; nb < 4; nb++)
                    mma16816(acc[mb][nb], ah[mb], &bh[nb * 2]);      // h*h
            ldsm4(bm,     sbh + (S_BM - S_BH) * GTILE + ko);
            ldsm4(bm + 4, sbh + (S_BM - S_BH) * GTILE + 16 * GPITCH + ko);
#pragma unroll
            for (int mb = 0; mb < 4; mb++)
#pragma unroll
                for (int nb = 0; nb < 4; nb++)
                    mma16816(acc[mb][nb], ah[mb], &bm[nb * 2]);      // h*m
#pragma unroll
            for (int mb = 0; mb < 4; mb++) {
                ldsm4(am, sah + S_AM * GTILE + mb * (16 * GPITCH) + ko);
#pragma unroll
                for (int nb = 0; nb < 4; nb++)
                    mma16816(acc[mb][nb], am, &bh[nb * 2]);          // m*h
            }
        }
    }

    const int g = lane >> 2, t = lane & 3;
#pragma unroll
    for (int mb = 0; mb < 4; mb++) {
#pragma unroll
        for (int nb = 0; nb < 4; nb++) {
            float* p0 = C + (size_t)(m0 + wm + mb * 16 + g) * Ndim + n0 + wn + nb * 8 + t * 2;
            float* p1 = p0 + 8 * Ndim;
            *(float2*)p0 = make_float2(acc[mb][nb][0], acc[mb][nb][1]);
            *(float2*)p1 = make_float2(acc[mb][nb][2], acc[mb][nb][3]);
        }
    }
#undef ISSUE
#undef ISSUE_SUB
}

// ---------------------------------------------------------------------------
// Fused causal entmax attention.
// Phase 2 (scores): fp32 register-blocked (flip-sensitive -> faithful).
// Phase 3: entmax per row (proven warp Michelot).
// Phase 4: P.V on TENSOR CORES (mma.sync bf16x3) -- flip-free path. Fragments
//          are built in registers from the fp32 score rows (sc) and the fp32
//          swizzled V tile via aligned float2 LDS + cvt to bf16x2 h/m pairs.
//          4 warps x n16 cover HD=64; 2 k-halves reduced through SMEM.
// Epilogue writes the bf16 h/m split of the attention output directly.
// ---------------------------------------------------------------------------
__global__ __launch_bounds__(256) void attn_kernel(
    const float* __restrict__ Q, const float* __restrict__ K,
    const float* __restrict__ V,
    __nv_bfloat16* __restrict__ AOh, __nv_bfloat16* __restrict__ AOm)
{
    extern __shared__ float sm[];
    float* sc = sm;                        // ROWS * SCP (padded pitch)
    float* qs = sm + ROWS * SCP;           // ROWS * HD
    float* kv = qs + ROWS * HD;            // 16384 floats (tile union)
    float4* kt4 = (float4*)kv;
    float4* vt4 = (float4*)kv;
    float* vts = kv;

    const int tid = threadIdx.x;
    const int hh = blockIdx.y;             // head
    const int r0 = blockIdx.x * ROWS;
    const int n_max = r0 + ROWS;
    const int ntiles = (n_max + COLT - 1) / COLT;

    // ---- Phase 1: q rows (scale folded in) ----
    for (int i = tid; i < ROWS * HD; i += 256) {
        int r = i >> 6, d = i & 63;
        qs[r * 64 + d] = Q[(size_t)(r0 + r) * DIM + hh * HD + d] * 0.125f;
    }

    // ---- Phase 2: scores (fp32, register-blocked) ----
    {
        const int cg = tid & 63;
        const int rg = tid >> 6;
        const int cs = cg & 15;

        for (int t = 0; t < ntiles; t++) {
            const int c0 = t * COLT;
            __syncthreads();
            {
                const float4* Kg = (const float4*)(K + (size_t)c0 * DIM + hh * HD);
#pragma unroll
                for (int it = 0; it < 16; it++) {
                    int i = it * 256 + tid;
                    int c = i >> 4, dq = i & 15;
                    kt4[c * 16 + (dq ^ ((c >> 2) & 15))] = Kg[(size_t)c * 256 + dq];
                }
            }
            __syncthreads();

            float acc[4][4];
#pragma unroll
            for (int i = 0; i < 4; i++)
#pragma unroll
                for (int j = 0; j < 4; j++) acc[i][j] = 0.f;

#pragma unroll
            for (int dq = 0; dq < 16; dq++) {
                float4 q0 = *(const float4*)&qs[(rg * 4 + 0) * 64 + dq * 4];
                float4 q1 = *(const float4*)&qs[(rg * 4 + 1) * 64 + dq * 4];
                float4 q2 = *(const float4*)&qs[(rg * 4 + 2) * 64 + dq * 4];
                float4 q3 = *(const float4*)&qs[(rg * 4 + 3) * 64 + dq * 4];
                float4 k0 = kt4[(cg * 4 + 0) * 16 + (dq ^ cs)];
                float4 k1 = kt4[(cg * 4 + 1) * 16 + (dq ^ cs)];
                float4 k2 = kt4[(cg * 4 + 2) * 16 + (dq ^ cs)];
                float4 k3 = kt4[(cg * 4 + 3) * 16 + (dq ^ cs)];
#define DOT4(a, b) (a.x * b.x + a.y * b.y + a.z * b.z + a.w * b.w)
                acc[0][0] += DOT4(q0, k0); acc[0][1] += DOT4(q0, k1);
                acc[0][2] += DOT4(q0, k2); acc[0][3] += DOT4(q0, k3);
                acc[1][0] += DOT4(q1, k0); acc[1][1] += DOT4(q1, k1);
                acc[1][2] += DOT4(q1, k2); acc[1][3] += DOT4(q1, k3);
                acc[2][0] += DOT4(q2, k0); acc[2][1] += DOT4(q2, k1);
                acc[2][2] += DOT4(q2, k2); acc[2][3] += DOT4(q2, k3);
                acc[3][0] += DOT4(q3, k0); acc[3][1] += DOT4(q3, k1);
                acc[3][2] += DOT4(q3, k2); acc[3][3] += DOT4(q3, k3);
            }
#pragma unroll
            for (int i = 0; i < 4; i++) {
                *(float4*)&sc[(size_t)(rg * 4 + i) * SCP + c0 + cg * 4] =
                    make_float4(acc[i][0], acc[i][1], acc[i][2], acc[i][3]);
            }
        }
    }
    __syncthreads();

    // ---- Phase 3: entmax per row (one warp per row, float4-vectorized) ----
    {
        const int w = tid >> 5, lane = tid & 31;
        const int tile_end = ntiles * COLT;
        for (int rr = w; rr < ROWS; rr += 8) {
            const int n = r0 + rr + 1;
            float* srow = sc + (size_t)rr * SCP;
            const float4* srow4 = (const float4*)srow;
            const int nv = n >> 2;
            const int ntail = nv << 2;

            float ssum = 0.f;
            for (int q = lane; q < nv; q += 32) {
                float4 v = srow4[q];
                ssum += (v.x + v.y) + (v.z + v.w);
            }
            for (int j = ntail + lane; j < n; j += 32) ssum += srow[j];
#pragma unroll
            for (int o = 16; o; o >>= 1) ssum += __shfl_xor_sync(0xFFFFFFFFu, ssum, o);

            int k = n;
            float tau = (ssum - 1.0f) / (float)n;
            for (int it = 0; it < SEQ; ++it) {
                float sa = 0.f; int ca = 0;
                for (int q = lane; q < nv; q += 32) {
                    float4 v = srow4[q];
                    if (v.x > tau) { sa += v.x; ca++; }
                    if (v.y > tau) { sa += v.y; ca++; }
                    if (v.z > tau) { sa += v.z; ca++; }
                    if (v.w > tau) { sa += v.w; ca++; }
                }
                for (int j = ntail + lane; j < n; j += 32) {
                    float v = srow[j];
                    if (v > tau) { sa += v; ca++; }
                }
#pragma unroll
                for (int o = 16; o; o >>= 1) {
                    sa += __shfl_xor_sync(0xFFFFFFFFu, sa, o);
                    ca += __shfl_xor_sync(0xFFFFFFFFu, ca, o);
                }
                if (ca == k) break;
                k = ca;
                tau = (sa - 1.0f) / (float)ca;
            }

            const float tau_star = (ssum - 1.0f) / (float)k;  // reference quirk: TOTAL sum

            float psum = 0.f;
            for (int q = lane; q < nv; q += 32) {
                float4 v = srow4[q];
                psum += fmaxf(v.x - tau_star, 0.f) + fmaxf(v.y - tau_star, 0.f)
                      + fmaxf(v.z - tau_star, 0.f) + fmaxf(v.w - tau_star, 0.f);
            }
            for (int j = ntail + lane; j < n; j += 32)
                psum += fmaxf(srow[j] - tau_star, 0.f);
#pragma unroll
            for (int o = 16; o; o >>= 1) psum += __shfl_xor_sync(0xFFFFFFFFu, psum, o);
            const float inv = 1.0f / (psum + 1e-10f);

            float4* srow4w = (float4*)srow;
            for (int q = lane; q < nv; q += 32) {
                float4 v = srow4w[q];
                srow4w[q] = make_float4(fmaxf(v.x - tau_star, 0.f) * inv,
                                        fmaxf(v.y - tau_star, 0.f) * inv,
                                        fmaxf(v.z - tau_star, 0.f) * inv,
                                        fmaxf(v.w - tau_star, 0.f) * inv);
            }
            for (int j = ntail + lane; j < n; j += 32)
                srow[j] = fmaxf(srow[j] - tau_star, 0.f) * inv;
            for (int j = n + lane; j < tile_end; j += 32) srow[j] = 0.f;
        }
    }

    // ---- Phase 4: O = P.V via mma.sync bf16x3 (flip-free path) ----
    {
        const int lane = tid & 31, warp = tid >> 5;
        const int wn2 = (warp & 3) * 16;       // this warp's 16-dim block
        const int khalf = warp >> 2;           // 0 or 1 (128-k half of each tile)
        const int fr = lane >> 2;              // fragment row group 0..7
        const int fc = (lane & 3) * 2;         // fragment col pair base

        float acc[2][4];
#pragma unroll
        for (int nb = 0; nb < 2; nb++)
#pragma unroll
            for (int q = 0; q < 4; q++) acc[nb][q] = 0.f;

        for (int t = 0; t < ntiles; t++) {
            const int c0 = t * COLT;
            __syncthreads();
            // V tile -> fp32 transposed swizzled smem (proven loader)
            {
                const float4* Vg = (const float4*)(V + (size_t)c0 * DIM + hh * HD);
#pragma unroll
                for (int it = 0; it < 16; it++) {
                    int i = it * 256 + tid;
                    int j = i >> 4, dq = i & 15;
                    float4 vv = Vg[(size_t)j * 256 + dq];
                    int jq = j >> 2, jr = j & 3;
                    int p = (jq ^ dq) * 4 + jr;
                    vts[(dq * 4 + 0) * 256 + p] = vv.x;
                    vts[(dq * 4 + 1) * 256 + p] = vv.y;
                    vts[(dq * 4 + 2) * 256 + p] = vv.z;
                    vts[(dq * 4 + 3) * 256 + p] = vv.w;
                }
            }
            __syncthreads();

            const int kbase = c0 + khalf * 128;
#pragma unroll
            for (int ks = 0; ks < 8; ks++) {
                const int k0 = kbase + ks * 16;
                // A (P) fragments from fp32 score rows
                float2 pa0 = *(const float2*)&sc[(size_t)fr * SCP + k0 + fc];
                float2 pa1 = *(const float2*)&sc[(size_t)(fr + 8) * SCP + k0 + fc];
                float2 pa2 = *(const float2*)&sc[(size_t)fr * SCP + k0 + fc + 8];
                float2 pa3 = *(const float2*)&sc[(size_t)(fr + 8) * SCP + k0 + fc + 8];
                uint32_t ah[4], am[4];
                ah[0] = bf2h(pa0); ah[1] = bf2h(pa1);
                ah[2] = bf2h(pa2); ah[3] = bf2h(pa3);
                am[0] = bf2m(pa0, ah[0]); am[1] = bf2m(pa1, ah[1]);
                am[2] = bf2m(pa2, ah[2]); am[3] = bf2m(pa3, ah[3]);

                const int kj = khalf * 128 + ks * 16 + fc;   // j within tile
#pragma unroll
                for (int nb = 0; nb < 2; nb++) {
                    const int d = wn2 + nb * 8 + fr;
                    const int swz = (d >> 2) & 15;
                    const int jq0 = kj >> 2, jr0 = kj & 3;
                    const int kj8 = kj + 8;
                    const int jq1 = kj8 >> 2, jr1 = kj8 & 3;
                    float2 vb0 = *(const float2*)&vts[d * 256 + ((jq0 ^ swz) << 2) + jr0];
                    float2 vb1 = *(const float2*)&vts[d * 256 + ((jq1 ^ swz) << 2) + jr1];
                    uint32_t bh[2], bm[2];
                    bh[0] = bf2h(vb0); bh[1] = bf2h(vb1);
                    bm[0] = bf2m(vb0, bh[0]); bm[1] = bf2m(vb1, bh[1]);
                    mma16816(acc[nb], ah, bh);   // h*h
                    mma16816(acc[nb], am, bh);   // m*h
                    mma16816(acc[nb], ah, bm);   // h*m
                }
            }
        }

        // reduce the two k-halves through SMEM, write bf16 h/m split
        __syncthreads();
        float* red = kv;   // [2][16][64] f32
#pragma unroll
        for (int nb = 0; nb < 2; nb++) {
            const int col = wn2 + nb * 8 + fc;
            red[khalf * 1024 + fr * 64 + col]           = acc[nb][0];
            red[khalf * 1024 + fr * 64 + col + 1]       = acc[nb][1];
            red[khalf * 1024 + (fr + 8) * 64 + col]     = acc[nb][2];
            red[khalf * 1024 + (fr + 8) * 64 + col + 1] = acc[nb][3];
        }
        __syncthreads();
        {
            const int m = tid >> 4, dq = tid & 15;
            float4 a = *(const float4*)&red[m * 64 + dq * 4];
            float4 b = *(const float4*)&red[1024 + m * 64 + dq * 4];
            float fv[4] = {a.x + b.x, a.y + b.y, a.z + b.z, a.w + b.w};
            __nv_bfloat16 bh[4], bm[4];
#pragma unroll
            for (int q = 0; q < 4; q++) {
                bh[q] = __float2bfloat16_rn(fv[q]);
                bm[q] = __float2bfloat16_rn(fv[q] - __bfloat162float(bh[q]));
            }
            size_t idx = (size_t)(r0 + m) * DIM + hh * HD + dq * 4;
            *(__nv_bfloat162*)&AOh[idx]     = __nv_bfloat162(bh[0], bh[1]);
            *(__nv_bfloat162*)&AOh[idx + 2] = __nv_bfloat162(bh[2], bh[3]);
            *(__nv_bfloat162*)&AOm[idx]     = __nv_bfloat162(bm[0], bm[1]);
            *(__nv_bfloat162*)&AOm[idx + 2] = __nv_bfloat162(bm[2], bm[3]);
        }
    }
}

// ---------------------------------------------------------------------------
extern "C" void kernel_launch(void* const* d_in, const int* in_sizes, int n_in,
                              void* d_out, int out_size)
{
    const float* x  = (const float*)d_in[0];
    const float* Wq = (const float*)d_in[1];
    const float* Wk = (const float*)d_in[2];
    const float* Wv = (const float*)d_in[3];
    const float* Wo = (const float*)d_in[4];
    float* out = (float*)d_out;

    float *Qp, *Kp, *Vp;
    cudaGetSymbolAddress((void**)&Qp, g_Q);
    cudaGetSymbolAddress((void**)&Kp, g_K);
    cudaGetSymbolAddress((void**)&Vp, g_V);

    __nv_bfloat16 *xh, *xm, *aoh, *aom, *wvh, *wvm, *woh, *wom;
    cudaGetSymbolAddress((void**)&xh,  g_xh);  cudaGetSymbolAddress((void**)&xm,  g_xm);
    cudaGetSymbolAddress((void**)&aoh, g_aoh); cudaGetSymbolAddress((void**)&aom, g_aom);
    cudaGetSymbolAddress((void**)&wvh, g_wvh); cudaGetSymbolAddress((void**)&wvm, g_wvm);
    cudaGetSymbolAddress((void**)&woh, g_woh); cudaGetSymbolAddress((void**)&wom, g_wom);

    const size_t attn_smem = (ROWS * SCP + ROWS * HD + 16384) * sizeof(float);
    cudaFuncSetAttribute(attn_kernel, cudaFuncAttributeMaxDynamicSharedMemorySize,
                         (int)attn_smem);
    cudaFuncSetAttribute(gemm_bf3, cudaFuncAttributeMaxDynamicSharedMemorySize, GSMEM);

    const int n4x = SEQ * DIM / 4;
    const int n4w = DIM * DIM / 4;

    // splits (flip-insensitive operands only)
    split2<<<n4x / 256, 256>>>(x,  xh,  xm,  n4x);
    split2<<<n4w / 256, 256>>>(Wv, wvh, wvm, n4w);
    split2<<<n4w / 256, 256>>>(Wo, woh, wom, n4w);

    {   // Q,K projections: fp32-faithful (entmax support is flip-sensitive)
        dim3 grid(DIM / 128, SEQ / 128, 2);
        sgemm_nt3<<<grid, 256>>>(x, Wq, Wk, Wk, Qp, Kp, Kp, DIM, DIM);
    }
    {   // V projection: bf16x3 tensor cores (errors pass linearly to output)
        dim3 grid(DIM / 128, SEQ / 128, 1);
        gemm_bf3<<<grid, 256, GSMEM>>>(xh, xm, wvh, wvm, Vp, DIM, DIM);
    }
    {   // fused entmax attention (tensor-core PV, writes bf16 h/m split)
        dim3 grid(SEQ / ROWS, NH);
        attn_kernel<<<grid, 256, attn_smem>>>(Qp, Kp, Vp, aoh, aom);
    }
    {   // output projection: bf16x3 tensor cores (post-entmax, flip-free)
        dim3 grid(DIM / 128, SEQ / 128, 1);
        gemm_bf3<<<grid, 256, GSMEM>>>(aoh, aom, woh, wom, out, DIM, DIM);
    }
}

// round 14
// speedup vs baseline: 1.1028x; 1.1028x over previous
#include <cuda_runtime.h>
#include <cuda_bf16.h>
#include <cstdint>
#include <cstddef>

#define SEQ 2048
#define DIM 1024
#define NH 16
#define HD 64
#define ROWS 16
#define COLT 256
#define SCP 2052   // padded score-row pitch (floats)

// phase-4 smem union layout (bytes, relative to union base)
#define VPITCH 528           // 256 bf16 = 512B data + 16B pad -> 4r mod 32 banks
#define OFF_VH 0
#define OFF_VM 33792         // 64 * 528
#define OFF_PH 67584
#define OFF_PM 76032         // OFF_PH + 16*528
#define UNION_BYTES 84480

// Scratch (allocation-free rule: __device__ globals)
__device__ float g_Q[SEQ * DIM];
__device__ float g_K[SEQ * DIM];

__device__ __nv_bfloat16 g_vth[DIM * SEQ];   // V transposed [dim][token], hi
__device__ __nv_bfloat16 g_vtm[DIM * SEQ];   // V transposed, residual
__device__ __nv_bfloat16 g_xh[SEQ * DIM], g_xm[SEQ * DIM];
__device__ __nv_bfloat16 g_aoh[SEQ * DIM], g_aom[SEQ * DIM];
__device__ __nv_bfloat16 g_wvh[DIM * DIM], g_wvm[DIM * DIM];
__device__ __nv_bfloat16 g_woh[DIM * DIM], g_wom[DIM * DIM];

// ===========================================================================
// Helpers
// ===========================================================================
__device__ __forceinline__ uint32_t smem_u32(const void* p) {
    uint32_t a;
    asm("{ .reg .u64 t; cvta.to.shared.u64 t, %1; cvt.u32.u64 %0, t; }"
        : "=r"(a) : "l"(p));
    return a;
}
__device__ __forceinline__ void ldsm4(uint32_t* r, uint32_t addr) {
    asm volatile("ldmatrix.sync.aligned.m8n8.x4.shared.b16 {%0,%1,%2,%3}, [%4];"
                 : "=r"(r[0]), "=r"(r[1]), "=r"(r[2]), "=r"(r[3]) : "r"(addr));
}
__device__ __forceinline__ void mma16816(float* c, const uint32_t* a, const uint32_t* b) {
    asm volatile(
        "mma.sync.aligned.m16n8k16.row.col.f32.bf16.bf16.f32 "
        "{%0,%1,%2,%3}, {%4,%5,%6,%7}, {%8,%9}, {%0,%1,%2,%3};"
        : "+f"(c[0]), "+f"(c[1]), "+f"(c[2]), "+f"(c[3])
        : "r"(a[0]), "r"(a[1]), "r"(a[2]), "r"(a[3]), "r"(b[0]), "r"(b[1]));
}
__device__ __forceinline__ void cp16(uint32_t s, const void* g) {
    asm volatile("cp.async.ca.shared.global [%0], [%1], 16;" :: "r"(s), "l"(g));
}
__device__ __forceinline__ uint32_t bf2h(float2 v) {
    __nv_bfloat162 b = __floats2bfloat162_rn(v.x, v.y);
    return *(uint32_t*)&b;
}
__device__ __forceinline__ uint32_t bf2m(float2 v, uint32_t hbits) {
    __nv_bfloat162 h = *(__nv_bfloat162*)&hbits;
    return bf2h(make_float2(v.x - __bfloat162float(h.x),
                            v.y - __bfloat162float(h.y)));
}

// ===========================================================================
// Split fp32 -> 2x bf16
// ===========================================================================
__global__ __launch_bounds__(256) void split2(
    const float* __restrict__ in, __nv_bfloat16* __restrict__ h,
    __nv_bfloat16* __restrict__ m, int n4)
{
    int i = blockIdx.x * 256 + threadIdx.x;
    if (i >= n4) return;
    float4 v = ((const float4*)in)[i];
    float f[4] = {v.x, v.y, v.z, v.w};
    __nv_bfloat16 hh[4], mm[4];
#pragma unroll
    for (int j = 0; j < 4; j++) {
        hh[j] = __float2bfloat16_rn(f[j]);
        mm[j] = __float2bfloat16_rn(f[j] - __bfloat162float(hh[j]));
    }
    ((__nv_bfloat162*)h)[i * 2 + 0] = __nv_bfloat162(hh[0], hh[1]);
    ((__nv_bfloat162*)h)[i * 2 + 1] = __nv_bfloat162(hh[2], hh[3]);
    ((__nv_bfloat162*)m)[i * 2 + 0] = __nv_bfloat162(mm[0], mm[1]);
    ((__nv_bfloat162*)m)[i * 2 + 1] = __nv_bfloat162(mm[2], mm[3]);
}

// ===========================================================================
// fp32 SIMT SGEMM (fp32-faithful Q/K path), double-buffered.
// ===========================================================================
__global__ __launch_bounds__(256, 2) void sgemm_nt3(
    const float* __restrict__ A,
    const float* __restrict__ B0, const float* __restrict__ B1, const float* __restrict__ B2,
    float* __restrict__ C0, float* __restrict__ C1, float* __restrict__ C2,
    int Kdim, int Ndim)
{
    const float* B = (blockIdx.z == 0) ? B0 : ((blockIdx.z == 1) ? B1 : B2);
    float* C = (blockIdx.z == 0) ? C0 : ((blockIdx.z == 1) ? C1 : C2);

    __shared__ __align__(16) float As[2][8][128];
    __shared__ __align__(16) float Bs[2][8][128];

    const int tid = threadIdx.x;
    const int m0 = blockIdx.y * 128;
    const int n0 = blockIdx.x * 128;
    const float* Ab = A + (size_t)m0 * Kdim;
    const float* Bb = B + (size_t)n0 * Kdim;

    const int lr = tid >> 1;
    const int lk = (tid & 1) * 4;

    const int warp = tid >> 5, lane = tid & 31;
    const int tr = (warp & 3) * 32 + (lane & 3) * 8;
    const int tc = (warp >> 2) * 64 + (lane >> 2) * 8;

    float acc[8][8];
#pragma unroll
    for (int i = 0; i < 8; i++)
#pragma unroll
        for (int j = 0; j < 8; j++) acc[i][j] = 0.f;

    const int NC = Kdim >> 3;
    for (int c = 0; c < NC; c++) {
        const int s = c & 1;
        const int k0 = c << 3;
        float4 a4 = *(const float4*)(Ab + (size_t)lr * Kdim + k0 + lk);
        float4 b4 = *(const float4*)(Bb + (size_t)lr * Kdim + k0 + lk);
        As[s][lk + 0][lr] = a4.x; As[s][lk + 1][lr] = a4.y;
        As[s][lk + 2][lr] = a4.z; As[s][lk + 3][lr] = a4.w;
        Bs[s][lk + 0][lr] = b4.x; Bs[s][lk + 1][lr] = b4.y;
        Bs[s][lk + 2][lr] = b4.z; Bs[s][lk + 3][lr] = b4.w;
        __syncthreads();
#pragma unroll
        for (int kk = 0; kk < 8; kk++) {
            float ar[8], br[8];
            *(float4*)(ar)     = *(const float4*)&As[s][kk][tr];
            *(float4*)(ar + 4) = *(const float4*)&As[s][kk][tr + 4];
            *(float4*)(br)     = *(const float4*)&Bs[s][kk][tc];
            *(float4*)(br + 4) = *(const float4*)&Bs[s][kk][tc + 4];
#pragma unroll
            for (int i = 0; i < 8; i++)
#pragma unroll
                for (int j = 0; j < 8; j++) acc[i][j] += ar[i] * br[j];
        }
    }

#pragma unroll
    for (int i = 0; i < 8; i++) {
        float* crow = C + (size_t)(m0 + tr + i) * Ndim + n0 + tc;
        *(float4*)(crow)     = make_float4(acc[i][0], acc[i][1], acc[i][2], acc[i][3]);
        *(float4*)(crow + 4) = make_float4(acc[i][4], acc[i][5], acc[i][6], acc[i][7]);
    }
}

// ===========================================================================
// bf16 3-term tensor-core GEMM core (shared by both variants)
// ===========================================================================
#define GPITCH 80
#define GTILE  (128 * GPITCH)
#define GSTAGE (4 * GTILE)
#define GSMEM  (3 * GSTAGE)
#define S_AH 0
#define S_AM 1
#define S_BH 2
#define S_BM 3

// VT=false: write fp32 C [M][Ndim].  VT=true: write bf16 h/m transposed
// [Ndim-rows][SEQ cols] (for the V tensor consumed by the attention kernel).
template <bool VT>
__global__ __launch_bounds__(256) void gemm_bf3_t(
    const __nv_bfloat16* __restrict__ Ah, const __nv_bfloat16* __restrict__ Am,
    const __nv_bfloat16* __restrict__ Bh, const __nv_bfloat16* __restrict__ Bm,
    float* __restrict__ C,
    __nv_bfloat16* __restrict__ CTh, __nv_bfloat16* __restrict__ CTm,
    int Kdim, int Ndim)
{
    extern __shared__ __align__(16) char smem[];

    const int tid = threadIdx.x;
    const int lane = tid & 31, warp = tid >> 5;
    const int m0 = blockIdx.y * 128;
    const int n0 = blockIdx.x * 128;
    const int wm = (warp >> 2) * 64;
    const int wn = (warp & 3) * 32;
    const int lr = tid >> 2;
    const int lq = tid & 3;

    const uint32_t sb = smem_u32(smem);
    const uint32_t aBase = sb + (uint32_t)(wm + (lane & 15)) * GPITCH + (lane >> 4) * 16;
    const uint32_t bBase = sb + (uint32_t)(wn + ((lane >> 4) << 3) + (lane & 7)) * GPITCH
                              + ((lane >> 3) & 1) * 16;

    float acc[4][4][4];
#pragma unroll
    for (int a = 0; a < 4; a++)
#pragma unroll
        for (int b = 0; b < 4; b++)
#pragma unroll
            for (int k = 0; k < 4; k++) acc[a][b][k] = 0.f;

    const int NC = Kdim >> 5;

#define ISSUE_SUB(G, row0, sub, st, k0)                                         \
    {                                                                           \
        _Pragma("unroll")                                                       \
        for (int it = 0; it < 2; it++) {                                        \
            int r = lr + it * 64;                                               \
            cp16(sb + (st) * GSTAGE + (sub) * GTILE + r * GPITCH + lq * 16,     \
                 (const char*)(G) + ((size_t)((row0) + r) * Kdim + (k0)) * 2 + lq * 16); \
        }                                                                       \
    }
#define ISSUE(ch, st)                                                           \
    {                                                                           \
        const int k0_ = (ch) * 32;                                              \
        ISSUE_SUB(Ah, m0, S_AH, st, k0_);                                       \
        ISSUE_SUB(Am, m0, S_AM, st, k0_);                                       \
        ISSUE_SUB(Bh, n0, S_BH, st, k0_);                                       \
        ISSUE_SUB(Bm, n0, S_BM, st, k0_);                                       \
        asm volatile("cp.async.commit_group;");                                 \
    }

    ISSUE(0, 0);
    ISSUE(1, 1);

    for (int c = 0; c < NC; c++) {
        const int st = c % 3;
        if (c + 1 < NC) asm volatile("cp.async.wait_group 1;");
        else            asm volatile("cp.async.wait_group 0;");
        __syncthreads();
        if (c + 2 < NC) ISSUE(c + 2, (c + 2) % 3);

        const uint32_t sah = aBase + st * GSTAGE;
        const uint32_t sbh = bBase + st * GSTAGE + S_BH * GTILE;
#pragma unroll
        for (int ks = 0; ks < 2; ks++) {
            const uint32_t ko = ks * 32;
            uint32_t ah[4][4], am[4], bh[8], bm[8];
#pragma unroll
            for (int mb = 0; mb < 4; mb++)
                ldsm4(ah[mb], sah + S_AH * GTILE + mb * (16 * GPITCH) + ko);
            ldsm4(bh,     sbh + ko);
            ldsm4(bh + 4, sbh + 16 * GPITCH + ko);
#pragma unroll
            for (int mb = 0; mb < 4; mb++)
#pragma unroll
                for (int nb = 0; nb < 4; nb++)
                    mma16816(acc[mb][nb], ah[mb], &bh[nb * 2]);      // h*h
            ldsm4(bm,     sbh + (S_BM - S_BH) * GTILE + ko);
            ldsm4(bm + 4, sbh + (S_BM - S_BH) * GTILE + 16 * GPITCH + ko);
#pragma unroll
            for (int mb = 0; mb < 4; mb++)
#pragma unroll
                for (int nb = 0; nb < 4; nb++)
                    mma16816(acc[mb][nb], ah[mb], &bm[nb * 2]);      // h*m
#pragma unroll
            for (int mb = 0; mb < 4; mb++) {
                ldsm4(am, sah + S_AM * GTILE + mb * (16 * GPITCH) + ko);
#pragma unroll
                for (int nb = 0; nb < 4; nb++)
                    mma16816(acc[mb][nb], am, &bh[nb * 2]);          // m*h
            }
        }
    }

    const int g = lane >> 2, t = lane & 3;
    if (!VT) {
#pragma unroll
        for (int mb = 0; mb < 4; mb++) {
#pragma unroll
            for (int nb = 0; nb < 4; nb++) {
                float* p0 = C + (size_t)(m0 + wm + mb * 16 + g) * Ndim + n0 + wn + nb * 8 + t * 2;
                float* p1 = p0 + 8 * Ndim;
                *(float2*)p0 = make_float2(acc[mb][nb][0], acc[mb][nb][1]);
                *(float2*)p1 = make_float2(acc[mb][nb][2], acc[mb][nb][3]);
            }
        }
    } else {
        // stage C tile fp32 in smem [128][132], then write transposed bf16 h/m
        __syncthreads();
        float* stage = (float*)smem;
#pragma unroll
        for (int mb = 0; mb < 4; mb++) {
#pragma unroll
            for (int nb = 0; nb < 4; nb++) {
                int row = wm + mb * 16 + g;
                int col = wn + nb * 8 + t * 2;
                stage[row * 132 + col]           = acc[mb][nb][0];
                stage[row * 132 + col + 1]       = acc[mb][nb][1];
                stage[(row + 8) * 132 + col]     = acc[mb][nb][2];
                stage[(row + 8) * 132 + col + 1] = acc[mb][nb][3];
            }
        }
        __syncthreads();
        const int c2 = tid & 127;      // local output col (VT row)
        const int half = tid >> 7;     // which 64-row half
#pragma unroll
        for (int it = 0; it < 8; it++) {
            const int mb0 = half * 64 + it * 8;
            uint32_t hq[4], mq[4];
#pragma unroll
            for (int e = 0; e < 4; e++) {
                float2 v = make_float2(stage[(mb0 + 2 * e) * 132 + c2],
                                       stage[(mb0 + 2 * e + 1) * 132 + c2]);
                hq[e] = bf2h(v);
                mq[e] = bf2m(v, hq[e]);
            }
            size_t idx = (size_t)(n0 + c2) * SEQ + m0 + mb0;
            *(uint4*)&CTh[idx] = make_uint4(hq[0], hq[1], hq[2], hq[3]);
            *(uint4*)&CTm[idx] = make_uint4(mq[0], mq[1], mq[2], mq[3]);
        }
    }
#undef ISSUE
#undef ISSUE_SUB
}

// ---------------------------------------------------------------------------
// Fused causal entmax attention.
// Phase 2: fp32 scores (flip-sensitive, faithful). Phase 3: warp Michelot.
// Phase 4: tensor-core P.V — V pre-converted bf16 h/m transposed (cp.async,
// zero conversion), P converted per tile (cheap), gemm_bf3's proven ldmatrix
// patterns, 2 k-half warpsets reduced through smem (R13-verified epilogue).
// ---------------------------------------------------------------------------
__global__ __launch_bounds__(256) void attn_kernel(
    const float* __restrict__ Q, const float* __restrict__ K,
    const __nv_bfloat16* __restrict__ VTh, const __nv_bfloat16* __restrict__ VTm,
    __nv_bfloat16* __restrict__ AOh, __nv_bfloat16* __restrict__ AOm)
{
    extern __shared__ float sm[];
    float* sc = sm;                        // ROWS * SCP
    float* qs = sm + ROWS * SCP;           // ROWS * HD
    float* kv = qs + ROWS * HD;            // union region (UNION_BYTES)
    float4* kt4 = (float4*)kv;
    char* Uc = (char*)kv;
    const uint32_t Ub = smem_u32(kv);

    const int tid = threadIdx.x;
    const int hh = blockIdx.y;
    const int r0 = blockIdx.x * ROWS;
    const int n_max = r0 + ROWS;
    const int ntiles = (n_max + COLT - 1) / COLT;

    // ---- Phase 1: q rows ----
    for (int i = tid; i < ROWS * HD; i += 256) {
        int r = i >> 6, d = i & 63;
        qs[r * 64 + d] = Q[(size_t)(r0 + r) * DIM + hh * HD + d] * 0.125f;
    }

    // ---- Phase 2: scores (fp32, register-blocked) ----
    {
        const int cg = tid & 63;
        const int rg = tid >> 6;
        const int cs = cg & 15;

        for (int t = 0; t < ntiles; t++) {
            const int c0 = t * COLT;
            __syncthreads();
            {
                const float4* Kg = (const float4*)(K + (size_t)c0 * DIM + hh * HD);
#pragma unroll
                for (int it = 0; it < 16; it++) {
                    int i = it * 256 + tid;
                    int c = i >> 4, dq = i & 15;
                    kt4[c * 16 + (dq ^ ((c >> 2) & 15))] = Kg[(size_t)c * 256 + dq];
                }
            }
            __syncthreads();

            float acc[4][4];
#pragma unroll
            for (int i = 0; i < 4; i++)
#pragma unroll
                for (int j = 0; j < 4; j++) acc[i][j] = 0.f;

#pragma unroll
            for (int dq = 0; dq < 16; dq++) {
                float4 q0 = *(const float4*)&qs[(rg * 4 + 0) * 64 + dq * 4];
                float4 q1 = *(const float4*)&qs[(rg * 4 + 1) * 64 + dq * 4];
                float4 q2 = *(const float4*)&qs[(rg * 4 + 2) * 64 + dq * 4];
                float4 q3 = *(const float4*)&qs[(rg * 4 + 3) * 64 + dq * 4];
                float4 k0 = kt4[(cg * 4 + 0) * 16 + (dq ^ cs)];
                float4 k1 = kt4[(cg * 4 + 1) * 16 + (dq ^ cs)];
                float4 k2 = kt4[(cg * 4 + 2) * 16 + (dq ^ cs)];
                float4 k3 = kt4[(cg * 4 + 3) * 16 + (dq ^ cs)];
#define DOT4(a, b) (a.x * b.x + a.y * b.y + a.z * b.z + a.w * b.w)
                acc[0][0] += DOT4(q0, k0); acc[0][1] += DOT4(q0, k1);
                acc[0][2] += DOT4(q0, k2); acc[0][3] += DOT4(q0, k3);
                acc[1][0] += DOT4(q1, k0); acc[1][1] += DOT4(q1, k1);
                acc[1][2] += DOT4(q1, k2); acc[1][3] += DOT4(q1, k3);
                acc[2][0] += DOT4(q2, k0); acc[2][1] += DOT4(q2, k1);
                acc[2][2] += DOT4(q2, k2); acc[2][3] += DOT4(q2, k3);
                acc[3][0] += DOT4(q3, k0); acc[3][1] += DOT4(q3, k1);
                acc[3][2] += DOT4(q3, k2); acc[3][3] += DOT4(q3, k3);
            }
#pragma unroll
            for (int i = 0; i < 4; i++) {
                *(float4*)&sc[(size_t)(rg * 4 + i) * SCP + c0 + cg * 4] =
                    make_float4(acc[i][0], acc[i][1], acc[i][2], acc[i][3]);
            }
        }
    }
    __syncthreads();

    // ---- Phase 3: entmax per row (warp Michelot, float4-vectorized) ----
    {
        const int w = tid >> 5, lane = tid & 31;
        const int tile_end = ntiles * COLT;
        for (int rr = w; rr < ROWS; rr += 8) {
            const int n = r0 + rr + 1;
            float* srow = sc + (size_t)rr * SCP;
            const float4* srow4 = (const float4*)srow;
            const int nv = n >> 2;
            const int ntail = nv << 2;

            float ssum = 0.f;
            for (int q = lane; q < nv; q += 32) {
                float4 v = srow4[q];
                ssum += (v.x + v.y) + (v.z + v.w);
            }
            for (int j = ntail + lane; j < n; j += 32) ssum += srow[j];
#pragma unroll
            for (int o = 16; o; o >>= 1) ssum += __shfl_xor_sync(0xFFFFFFFFu, ssum, o);

            int k = n;
            float tau = (ssum - 1.0f) / (float)n;
            for (int it = 0; it < SEQ; ++it) {
                float sa = 0.f; int ca = 0;
                for (int q = lane; q < nv; q += 32) {
                    float4 v = srow4[q];
                    if (v.x > tau) { sa += v.x; ca++; }
                    if (v.y > tau) { sa += v.y; ca++; }
                    if (v.z > tau) { sa += v.z; ca++; }
                    if (v.w > tau) { sa += v.w; ca++; }
                }
                for (int j = ntail + lane; j < n; j += 32) {
                    float v = srow[j];
                    if (v > tau) { sa += v; ca++; }
                }
#pragma unroll
                for (int o = 16; o; o >>= 1) {
                    sa += __shfl_xor_sync(0xFFFFFFFFu, sa, o);
                    ca += __shfl_xor_sync(0xFFFFFFFFu, ca, o);
                }
                if (ca == k) break;
                k = ca;
                tau = (sa - 1.0f) / (float)ca;
            }

            const float tau_star = (ssum - 1.0f) / (float)k;  // reference quirk: TOTAL sum

            float psum = 0.f;
            for (int q = lane; q < nv; q += 32) {
                float4 v = srow4[q];
                psum += fmaxf(v.x - tau_star, 0.f) + fmaxf(v.y - tau_star, 0.f)
                      + fmaxf(v.z - tau_star, 0.f) + fmaxf(v.w - tau_star, 0.f);
            }
            for (int j = ntail + lane; j < n; j += 32)
                psum += fmaxf(srow[j] - tau_star, 0.f);
#pragma unroll
            for (int o = 16; o; o >>= 1) psum += __shfl_xor_sync(0xFFFFFFFFu, psum, o);
            const float inv = 1.0f / (psum + 1e-10f);

            float4* srow4w = (float4*)srow;
            for (int q = lane; q < nv; q += 32) {
                float4 v = srow4w[q];
                srow4w[q] = make_float4(fmaxf(v.x - tau_star, 0.f) * inv,
                                        fmaxf(v.y - tau_star, 0.f) * inv,
                                        fmaxf(v.z - tau_star, 0.f) * inv,
                                        fmaxf(v.w - tau_star, 0.f) * inv);
            }
            for (int j = ntail + lane; j < n; j += 32)
                srow[j] = fmaxf(srow[j] - tau_star, 0.f) * inv;
            for (int j = n + lane; j < tile_end; j += 32) srow[j] = 0.f;
        }
    }

    // ---- Phase 4: O = P.V, tensor cores ----
    {
        const int lane = tid & 31, warp = tid >> 5;
        const int kq = warp >> 2;            // k-half of each 256-tile
        const int wn = (warp & 3) * 16;      // 16-dim block

        const uint32_t aBase = Ub + OFF_PH + (uint32_t)(lane & 15) * VPITCH
                                          + (lane >> 4) * 16;
        const uint32_t bBase = Ub + OFF_VH
                             + (uint32_t)(wn + ((lane >> 4) << 3) + (lane & 7)) * VPITCH
                             + ((lane >> 3) & 1) * 16;

        float acc[2][4];
#pragma unroll
        for (int nb = 0; nb < 2; nb++)
#pragma unroll
            for (int q = 0; q < 4; q++) acc[nb][q] = 0.f;

        for (int t = 0; t < ntiles; t++) {
            const int c0 = t * COLT;
            __syncthreads();
            // cp.async V h/m tiles: [d rows 64][j 256 bf16], pitch VPITCH
            {
                const char* srcH = (const char*)(VTh + (size_t)hh * 64 * SEQ + c0);
                const char* srcM = (const char*)(VTm + (size_t)hh * 64 * SEQ + c0);
#pragma unroll
                for (int s = 0; s < 8; s++) {
                    int idx = s * 256 + tid;
                    int d = idx >> 5, seg = idx & 31;
                    cp16(Ub + OFF_VH + d * VPITCH + seg * 16,
                         srcH + (size_t)d * SEQ * 2 + seg * 16);
                    cp16(Ub + OFF_VM + d * VPITCH + seg * 16,
                         srcM + (size_t)d * SEQ * 2 + seg * 16);
                }
                asm volatile("cp.async.commit_group;");
            }
            // P tile fp32 -> bf16 h/m
#pragma unroll
            for (int s = 0; s < 8; s++) {
                int p = s * 256 + tid;
                int r = p >> 7, jp = p & 127;
                float2 v = *(const float2*)&sc[(size_t)r * SCP + c0 + jp * 2];
                uint32_t hb = bf2h(v);
                uint32_t mb = bf2m(v, hb);
                *(uint32_t*)(Uc + OFF_PH + r * VPITCH + jp * 4) = hb;
                *(uint32_t*)(Uc + OFF_PM + r * VPITCH + jp * 4) = mb;
            }
            asm volatile("cp.async.wait_group 0;");
            __syncthreads();

#pragma unroll
            for (int ks = 0; ks < 8; ks++) {
                const uint32_t ko = kq * 256 + ks * 32;
                uint32_t ah[4], am[4], bh[4], bm[4];
                ldsm4(ah, aBase + ko);
                ldsm4(bh, bBase + ko);
                ldsm4(am, aBase + (OFF_PM - OFF_PH) + ko);
                ldsm4(bm, bBase + (OFF_VM - OFF_VH) + ko);
                mma16816(acc[0], ah, &bh[0]);
                mma16816(acc[1], ah, &bh[2]);
                mma16816(acc[0], am, &bh[0]);
                mma16816(acc[1], am, &bh[2]);
                mma16816(acc[0], ah, &bm[0]);
                mma16816(acc[1], ah, &bm[2]);
            }
        }

        // reduce the two k-halves through SMEM, write bf16 h/m split
        __syncthreads();
        float* red = kv;   // [2][16][64]
        const int g = lane >> 2, tt = lane & 3;
#pragma unroll
        for (int nb = 0; nb < 2; nb++) {
            const int col = wn + nb * 8 + tt * 2;
            red[kq * 1024 + g * 64 + col]           = acc[nb][0];
            red[kq * 1024 + g * 64 + col + 1]       = acc[nb][1];
            red[kq * 1024 + (g + 8) * 64 + col]     = acc[nb][2];
            red[kq * 1024 + (g + 8) * 64 + col + 1] = acc[nb][3];
        }
        __syncthreads();
        {
            const int m = tid >> 4, dq = tid & 15;
            float4 a = *(const float4*)&red[m * 64 + dq * 4];
            float4 b = *(const float4*)&red[1024 + m * 64 + dq * 4];
            float fv[4] = {a.x + b.x, a.y + b.y, a.z + b.z, a.w + b.w};
            __nv_bfloat16 bh[4], bm[4];
#pragma unroll
            for (int q = 0; q < 4; q++) {
                bh[q] = __float2bfloat16_rn(fv[q]);
                bm[q] = __float2bfloat16_rn(fv[q] - __bfloat162float(bh[q]));
            }
            size_t idx = (size_t)(r0 + m) * DIM + hh * HD + dq * 4;
            *(__nv_bfloat162*)&AOh[idx]     = __nv_bfloat162(bh[0], bh[1]);
            *(__nv_bfloat162*)&AOh[idx + 2] = __nv_bfloat162(bh[2], bh[3]);
            *(__nv_bfloat162*)&AOm[idx]     = __nv_bfloat162(bm[0], bm[1]);
            *(__nv_bfloat162*)&AOm[idx + 2] = __nv_bfloat162(bm[2], bm[3]);
        }
    }
}

// ---------------------------------------------------------------------------
extern "C" void kernel_launch(void* const* d_in, const int* in_sizes, int n_in,
                              void* d_out, int out_size)
{
    const float* x  = (const float*)d_in[0];
    const float* Wq = (const float*)d_in[1];
    const float* Wk = (const float*)d_in[2];
    const float* Wv = (const float*)d_in[3];
    const float* Wo = (const float*)d_in[4];
    float* out = (float*)d_out;

    float *Qp, *Kp;
    cudaGetSymbolAddress((void**)&Qp, g_Q);
    cudaGetSymbolAddress((void**)&Kp, g_K);

    __nv_bfloat16 *vth, *vtm, *xh, *xm, *aoh, *aom, *wvh, *wvm, *woh, *wom;
    cudaGetSymbolAddress((void**)&vth, g_vth); cudaGetSymbolAddress((void**)&vtm, g_vtm);
    cudaGetSymbolAddress((void**)&xh,  g_xh);  cudaGetSymbolAddress((void**)&xm,  g_xm);
    cudaGetSymbolAddress((void**)&aoh, g_aoh); cudaGetSymbolAddress((void**)&aom, g_aom);
    cudaGetSymbolAddress((void**)&wvh, g_wvh); cudaGetSymbolAddress((void**)&wvm, g_wvm);
    cudaGetSymbolAddress((void**)&woh, g_woh); cudaGetSymbolAddress((void**)&wom, g_wom);

    const size_t attn_smem = (ROWS * SCP + ROWS * HD) * sizeof(float) + UNION_BYTES;
    cudaFuncSetAttribute(attn_kernel, cudaFuncAttributeMaxDynamicSharedMemorySize,
                         (int)attn_smem);
    cudaFuncSetAttribute(gemm_bf3_t<false>, cudaFuncAttributeMaxDynamicSharedMemorySize, GSMEM);
    cudaFuncSetAttribute(gemm_bf3_t<true>,  cudaFuncAttributeMaxDynamicSharedMemorySize, GSMEM);

    const int n4x = SEQ * DIM / 4;
    const int n4w = DIM * DIM / 4;

    split2<<<n4x / 256, 256>>>(x,  xh,  xm,  n4x);
    split2<<<n4w / 256, 256>>>(Wv, wvh, wvm, n4w);
    split2<<<n4w / 256, 256>>>(Wo, woh, wom, n4w);

    {   // Q,K projections: fp32-faithful (flip-sensitive)
        dim3 grid(DIM / 128, SEQ / 128, 2);
        sgemm_nt3<<<grid, 256>>>(x, Wq, Wk, Wk, Qp, Kp, Kp, DIM, DIM);
    }
    {   // V projection: bf16x3 tensor cores, writes TRANSPOSED bf16 h/m
        dim3 grid(DIM / 128, SEQ / 128, 1);
        gemm_bf3_t<true><<<grid, 256, GSMEM>>>(xh, xm, wvh, wvm,
                                               nullptr, vth, vtm, DIM, DIM);
    }
    {   // fused entmax attention (tensor-core PV)
        dim3 grid(SEQ / ROWS, NH);
        attn_kernel<<<grid, 256, attn_smem>>>(Qp, Kp, vth, vtm, aoh, aom);
    }
    {   // output projection: bf16x3 tensor cores
        dim3 grid(DIM / 128, SEQ / 128, 1);
        gemm_bf3_t<false><<<grid, 256, GSMEM>>>(aoh, aom, woh, wom,
                                                out, nullptr, nullptr, DIM, DIM);
    }
}

// round 15
// speedup vs baseline: 1.2078x; 1.0952x over previous
#include <cuda_runtime.h>
#include <cuda_bf16.h>
#include <cstdint>
#include <cstddef>

#define SEQ 2048
#define DIM 1024
#define NH 16
#define HD 64
#define ROWS 16
#define COLT 256
#define SCP 2052   // padded score-row pitch (floats)

// q/k split tile pitch (bytes): 64 bf16 = 128B + 16B pad -> conflict-free
#define QSP 144
// K-tile split offsets within union (128 rows x QSP per split)
#define OFF_KH 0
#define OFF_KM 18432
#define OFF_KL 36864

// phase-4 smem union layout (bytes, relative to union base)
#define VPITCH 528
#define OFF_VH 0
#define OFF_VM 33792
#define OFF_PH 67584
#define OFF_PM 76032
#define UNION_BYTES 84480

// Scratch (allocation-free rule: __device__ globals)
__device__ __nv_bfloat16 g_qh[SEQ * DIM], g_qm[SEQ * DIM], g_ql[SEQ * DIM];
__device__ __nv_bfloat16 g_kh[SEQ * DIM], g_km[SEQ * DIM], g_kl[SEQ * DIM];
__device__ __nv_bfloat16 g_vth[DIM * SEQ];   // V transposed [dim][token], hi
__device__ __nv_bfloat16 g_vtm[DIM * SEQ];   // V transposed, residual
__device__ __nv_bfloat16 g_xh[SEQ * DIM], g_xm[SEQ * DIM];
__device__ __nv_bfloat16 g_aoh[SEQ * DIM], g_aom[SEQ * DIM];
__device__ __nv_bfloat16 g_wvh[DIM * DIM], g_wvm[DIM * DIM];
__device__ __nv_bfloat16 g_woh[DIM * DIM], g_wom[DIM * DIM];

// ===========================================================================
// Helpers
// ===========================================================================
__device__ __forceinline__ uint32_t smem_u32(const void* p) {
    uint32_t a;
    asm("{ .reg .u64 t; cvta.to.shared.u64 t, %1; cvt.u32.u64 %0, t; }"
        : "=r"(a) : "l"(p));
    return a;
}
__device__ __forceinline__ void ldsm4(uint32_t* r, uint32_t addr) {
    asm volatile("ldmatrix.sync.aligned.m8n8.x4.shared.b16 {%0,%1,%2,%3}, [%4];"
                 : "=r"(r[0]), "=r"(r[1]), "=r"(r[2]), "=r"(r[3]) : "r"(addr));
}
__device__ __forceinline__ void mma16816(float* c, const uint32_t* a, const uint32_t* b) {
    asm volatile(
        "mma.sync.aligned.m16n8k16.row.col.f32.bf16.bf16.f32 "
        "{%0,%1,%2,%3}, {%4,%5,%6,%7}, {%8,%9}, {%0,%1,%2,%3};"
        : "+f"(c[0]), "+f"(c[1]), "+f"(c[2]), "+f"(c[3])
        : "r"(a[0]), "r"(a[1]), "r"(a[2]), "r"(a[3]), "r"(b[0]), "r"(b[1]));
}
__device__ __forceinline__ void cp16(uint32_t s, const void* g) {
    asm volatile("cp.async.ca.shared.global [%0], [%1], 16;" :: "r"(s), "l"(g));
}
__device__ __forceinline__ uint32_t bf2h(float2 v) {
    __nv_bfloat162 b = __floats2bfloat162_rn(v.x, v.y);
    return *(uint32_t*)&b;
}
__device__ __forceinline__ uint32_t bf2m(float2 v, uint32_t hbits) {
    __nv_bfloat162 h = *(__nv_bfloat162*)&hbits;
    return bf2h(make_float2(v.x - __bfloat162float(h.x),
                            v.y - __bfloat162float(h.y)));
}
// fp32 pair -> bf16 h + m + l triple (captures ~24 mantissa bits)
__device__ __forceinline__ void split3_f2(float2 v, uint32_t& H, uint32_t& M, uint32_t& L) {
    H = bf2h(v);
    __nv_bfloat162 h2 = *(__nv_bfloat162*)&H;
    float2 r1 = make_float2(v.x - __bfloat162float(h2.x),
                            v.y - __bfloat162float(h2.y));
    M = bf2h(r1);
    __nv_bfloat162 m2 = *(__nv_bfloat162*)&M;
    float2 r2 = make_float2(r1.x - __bfloat162float(m2.x),
                            r1.y - __bfloat162float(m2.y));
    L = bf2h(r2);
}

// ===========================================================================
// Split fp32 -> 2x bf16
// ===========================================================================
__global__ __launch_bounds__(256) void split2(
    const float* __restrict__ in, __nv_bfloat16* __restrict__ h,
    __nv_bfloat16* __restrict__ m, int n4)
{
    int i = blockIdx.x * 256 + threadIdx.x;
    if (i >= n4) return;
    float4 v = ((const float4*)in)[i];
    float f[4] = {v.x, v.y, v.z, v.w};
    __nv_bfloat16 hh[4], mm[4];
#pragma unroll
    for (int j = 0; j < 4; j++) {
        hh[j] = __float2bfloat16_rn(f[j]);
        mm[j] = __float2bfloat16_rn(f[j] - __bfloat162float(hh[j]));
    }
    ((__nv_bfloat162*)h)[i * 2 + 0] = __nv_bfloat162(hh[0], hh[1]);
    ((__nv_bfloat162*)h)[i * 2 + 1] = __nv_bfloat162(hh[2], hh[3]);
    ((__nv_bfloat162*)m)[i * 2 + 0] = __nv_bfloat162(mm[0], mm[1]);
    ((__nv_bfloat162*)m)[i * 2 + 1] = __nv_bfloat162(mm[2], mm[3]);
}

// ===========================================================================
// fp32 SIMT SGEMM for Q,K (fp32-faithful accumulation), double-buffered.
// Epilogue writes bf16 h/m/l triples (scale 0.125 folded for Q, exact).
// blockIdx.z: 0 = Q (Wq, scaled), 1 = K (Wk).
// ===========================================================================
__global__ __launch_bounds__(256, 2) void sgemm_split(
    const float* __restrict__ A,
    const float* __restrict__ Bq, const float* __restrict__ Bk,
    __nv_bfloat16* __restrict__ qh, __nv_bfloat16* __restrict__ qm,
    __nv_bfloat16* __restrict__ ql,
    __nv_bfloat16* __restrict__ kh, __nv_bfloat16* __restrict__ km,
    __nv_bfloat16* __restrict__ kl,
    int Kdim, int Ndim)
{
    const int z = blockIdx.z;
    const float* B = z ? Bk : Bq;
    __nv_bfloat16* oh = z ? kh : qh;
    __nv_bfloat16* om = z ? km : qm;
    __nv_bfloat16* ol = z ? kl : ql;
    const float scl = z ? 1.0f : 0.125f;

    __shared__ __align__(16) float As[2][8][128];
    __shared__ __align__(16) float Bs[2][8][128];

    const int tid = threadIdx.x;
    const int m0 = blockIdx.y * 128;
    const int n0 = blockIdx.x * 128;
    const float* Ab = A + (size_t)m0 * Kdim;
    const float* Bb = B + (size_t)n0 * Kdim;

    const int lr = tid >> 1;
    const int lk = (tid & 1) * 4;

    const int warp = tid >> 5, lane = tid & 31;
    const int tr = (warp & 3) * 32 + (lane & 3) * 8;
    const int tc = (warp >> 2) * 64 + (lane >> 2) * 8;

    float acc[8][8];
#pragma unroll
    for (int i = 0; i < 8; i++)
#pragma unroll
        for (int j = 0; j < 8; j++) acc[i][j] = 0.f;

    const int NC = Kdim >> 3;
    for (int c = 0; c < NC; c++) {
        const int s = c & 1;
        const int k0 = c << 3;
        float4 a4 = *(const float4*)(Ab + (size_t)lr * Kdim + k0 + lk);
        float4 b4 = *(const float4*)(Bb + (size_t)lr * Kdim + k0 + lk);
        As[s][lk + 0][lr] = a4.x; As[s][lk + 1][lr] = a4.y;
        As[s][lk + 2][lr] = a4.z; As[s][lk + 3][lr] = a4.w;
        Bs[s][lk + 0][lr] = b4.x; Bs[s][lk + 1][lr] = b4.y;
        Bs[s][lk + 2][lr] = b4.z; Bs[s][lk + 3][lr] = b4.w;
        __syncthreads();
#pragma unroll
        for (int kk = 0; kk < 8; kk++) {
            float ar[8], br[8];
            *(float4*)(ar)     = *(const float4*)&As[s][kk][tr];
            *(float4*)(ar + 4) = *(const float4*)&As[s][kk][tr + 4];
            *(float4*)(br)     = *(const float4*)&Bs[s][kk][tc];
            *(float4*)(br + 4) = *(const float4*)&Bs[s][kk][tc + 4];
#pragma unroll
            for (int i = 0; i < 8; i++)
#pragma unroll
                for (int j = 0; j < 8; j++) acc[i][j] += ar[i] * br[j];
        }
    }

#pragma unroll
    for (int i = 0; i < 8; i++) {
        size_t base = (size_t)(m0 + tr + i) * Ndim + n0 + tc;
        uint32_t H[4], M[4], L[4];
#pragma unroll
        for (int e = 0; e < 4; e++) {
            float2 v = make_float2(acc[i][2 * e] * scl, acc[i][2 * e + 1] * scl);
            split3_f2(v, H[e], M[e], L[e]);
        }
        *(uint4*)&oh[base] = make_uint4(H[0], H[1], H[2], H[3]);
        *(uint4*)&om[base] = make_uint4(M[0], M[1], M[2], M[3]);
        *(uint4*)&ol[base] = make_uint4(L[0], L[1], L[2], L[3]);
    }
}

// ===========================================================================
// bf16 3-term tensor-core GEMM (V projection / Wo projection)
// ===========================================================================
#define GPITCH 80
#define GTILE  (128 * GPITCH)
#define GSTAGE (4 * GTILE)
#define GSMEM  (3 * GSTAGE)
#define S_AH 0
#define S_AM 1
#define S_BH 2
#define S_BM 3

template <bool VT>
__global__ __launch_bounds__(256) void gemm_bf3_t(
    const __nv_bfloat16* __restrict__ Ah, const __nv_bfloat16* __restrict__ Am,
    const __nv_bfloat16* __restrict__ Bh, const __nv_bfloat16* __restrict__ Bm,
    float* __restrict__ C,
    __nv_bfloat16* __restrict__ CTh, __nv_bfloat16* __restrict__ CTm,
    int Kdim, int Ndim)
{
    extern __shared__ __align__(16) char smem[];

    const int tid = threadIdx.x;
    const int lane = tid & 31, warp = tid >> 5;
    const int m0 = blockIdx.y * 128;
    const int n0 = blockIdx.x * 128;
    const int wm = (warp >> 2) * 64;
    const int wn = (warp & 3) * 32;
    const int lr = tid >> 2;
    const int lq = tid & 3;

    const uint32_t sb = smem_u32(smem);
    const uint32_t aBase = sb + (uint32_t)(wm + (lane & 15)) * GPITCH + (lane >> 4) * 16;
    const uint32_t bBase = sb + (uint32_t)(wn + ((lane >> 4) << 3) + (lane & 7)) * GPITCH
                              + ((lane >> 3) & 1) * 16;

    float acc[4][4][4];
#pragma unroll
    for (int a = 0; a < 4; a++)
#pragma unroll
        for (int b = 0; b < 4; b++)
#pragma unroll
            for (int k = 0; k < 4; k++) acc[a][b][k] = 0.f;

    const int NC = Kdim >> 5;

#define ISSUE_SUB(G, row0, sub, st, k0)                                         \
    {                                                                           \
        _Pragma("unroll")                                                       \
        for (int it = 0; it < 2; it++) {                                        \
            int r = lr + it * 64;                                               \
            cp16(sb + (st) * GSTAGE + (sub) * GTILE + r * GPITCH + lq * 16,     \
                 (const char*)(G) + ((size_t)((row0) + r) * Kdim + (k0)) * 2 + lq * 16); \
        }                                                                       \
    }
#define ISSUE(ch, st)                                                           \
    {                                                                           \
        const int k0_ = (ch) * 32;                                              \
        ISSUE_SUB(Ah, m0, S_AH, st, k0_);                                       \
        ISSUE_SUB(Am, m0, S_AM, st, k0_);                                       \
        ISSUE_SUB(Bh, n0, S_BH, st, k0_);                                       \
        ISSUE_SUB(Bm, n0, S_BM, st, k0_);                                       \
        asm volatile("cp.async.commit_group;");                                 \
    }

    ISSUE(0, 0);
    ISSUE(1, 1);

    for (int c = 0; c < NC; c++) {
        const int st = c % 3;
        if (c + 1 < NC) asm volatile("cp.async.wait_group 1;");
        else            asm volatile("cp.async.wait_group 0;");
        __syncthreads();
        if (c + 2 < NC) ISSUE(c + 2, (c + 2) % 3);

        const uint32_t sah = aBase + st * GSTAGE;
        const uint32_t sbh = bBase + st * GSTAGE + S_BH * GTILE;
#pragma unroll
        for (int ks = 0; ks < 2; ks++) {
            const uint32_t ko = ks * 32;
            uint32_t ah[4][4], am[4], bh[8], bm[8];
#pragma unroll
            for (int mb = 0; mb < 4; mb++)
                ldsm4(ah[mb], sah + S_AH * GTILE + mb * (16 * GPITCH) + ko);
            ldsm4(bh,     sbh + ko);
            ldsm4(bh + 4, sbh + 16 * GPITCH + ko);
#pragma unroll
            for (int mb = 0; mb < 4; mb++)
#pragma unroll
                for (int nb = 0; nb < 4; nb++)
                    mma16816(acc[mb][nb], ah[mb], &bh[nb * 2]);      // h*h
            ldsm4(bm,     sbh + (S_BM - S_BH) * GTILE + ko);
            ldsm4(bm + 4, sbh + (S_BM - S_BH) * GTILE + 16 * GPITCH + ko);
#pragma unroll
            for (int mb = 0; mb < 4; mb++)
#pragma unroll
                for (int nb = 0; nb < 4; nb++)
                    mma16816(acc[mb][nb], ah[mb], &bm[nb * 2]);      // h*m
#pragma unroll
            for (int mb = 0; mb < 4; mb++) {
                ldsm4(am, sah + S_AM * GTILE + mb * (16 * GPITCH) + ko);
#pragma unroll
                for (int nb = 0; nb < 4; nb++)
                    mma16816(acc[mb][nb], am, &bh[nb * 2]);          // m*h
            }
        }
    }

    const int g = lane >> 2, t = lane & 3;
    if (!VT) {
#pragma unroll
        for (int mb = 0; mb < 4; mb++) {
#pragma unroll
            for (int nb = 0; nb < 4; nb++) {
                float* p0 = C + (size_t)(m0 + wm + mb * 16 + g) * Ndim + n0 + wn + nb * 8 + t * 2;
                float* p1 = p0 + 8 * Ndim;
                *(float2*)p0 = make_float2(acc[mb][nb][0], acc[mb][nb][1]);
                *(float2*)p1 = make_float2(acc[mb][nb][2], acc[mb][nb][3]);
            }
        }
    } else {
        __syncthreads();
        float* stage = (float*)smem;
#pragma unroll
        for (int mb = 0; mb < 4; mb++) {
#pragma unroll
            for (int nb = 0; nb < 4; nb++) {
                int row = wm + mb * 16 + g;
                int col = wn + nb * 8 + t * 2;
                stage[row * 132 + col]           = acc[mb][nb][0];
                stage[row * 132 + col + 1]       = acc[mb][nb][1];
                stage[(row + 8) * 132 + col]     = acc[mb][nb][2];
                stage[(row + 8) * 132 + col + 1] = acc[mb][nb][3];
            }
        }
        __syncthreads();
        const int c2 = tid & 127;
        const int half = tid >> 7;
#pragma unroll
        for (int it = 0; it < 8; it++) {
            const int mb0 = half * 64 + it * 8;
            uint32_t hq[4], mq[4];
#pragma unroll
            for (int e = 0; e < 4; e++) {
                float2 v = make_float2(stage[(mb0 + 2 * e) * 132 + c2],
                                       stage[(mb0 + 2 * e + 1) * 132 + c2]);
                hq[e] = bf2h(v);
                mq[e] = bf2m(v, hq[e]);
            }
            size_t idx = (size_t)(n0 + c2) * SEQ + m0 + mb0;
            *(uint4*)&CTh[idx] = make_uint4(hq[0], hq[1], hq[2], hq[3]);
            *(uint4*)&CTm[idx] = make_uint4(mq[0], mq[1], mq[2], mq[3]);
        }
    }
#undef ISSUE
#undef ISSUE_SUB
}

// ---------------------------------------------------------------------------
// Fused causal entmax attention.
// Phase 2: QK^T scores via mma.sync 8-term bf16 h/m/l (fp32-grade: dropped
//          term <= 2^-32; validated error model from R5/R6 failures).
// Phase 3: warp Michelot entmax (fp32, unchanged).
// Phase 4: tensor-core P.V (R14-proven).
// ---------------------------------------------------------------------------
__global__ __launch_bounds__(256) void attn_kernel(
    const __nv_bfloat16* __restrict__ Qh, const __nv_bfloat16* __restrict__ Qm,
    const __nv_bfloat16* __restrict__ Ql,
    const __nv_bfloat16* __restrict__ Kh, const __nv_bfloat16* __restrict__ Km,
    const __nv_bfloat16* __restrict__ Kl,
    const __nv_bfloat16* __restrict__ VTh, const __nv_bfloat16* __restrict__ VTm,
    __nv_bfloat16* __restrict__ AOh, __nv_bfloat16* __restrict__ AOm)
{
    extern __shared__ float sm[];
    float* sc = sm;                          // ROWS * SCP floats
    char* Qr = (char*)(sm + ROWS * SCP);     // 6912 B: Q h/m/l tiles
    char* Uc = Qr + 3 * 16 * QSP;            // union region (UNION_BYTES)
    float* kv = (float*)Uc;
    const uint32_t Qb = smem_u32(Qr);
    const uint32_t Ub = smem_u32(Uc);

    const int tid = threadIdx.x;
    const int lane = tid & 31, warp = tid >> 5;
    const int hh = blockIdx.y;
    const int r0 = blockIdx.x * ROWS;
    const int n_max = r0 + ROWS;

    // ---- Phase 2a: load Q h/m/l tiles (16 x 64) ----
    if (tid < 128) {
        int r = tid >> 3, seg = tid & 7;
        size_t g = (size_t)(r0 + r) * DIM + hh * HD + seg * 8;
        cp16(Qb + 0 * 2304 + r * QSP + seg * 16, Qh + g);
        cp16(Qb + 1 * 2304 + r * QSP + seg * 16, Qm + g);
        cp16(Qb + 2 * 2304 + r * QSP + seg * 16, Ql + g);
    }
    asm volatile("cp.async.commit_group;");
    asm volatile("cp.async.wait_group 0;");
    __syncthreads();

    // A-fragments (Q) into registers, once
    uint32_t qa[3][4][4];
    {
        const uint32_t aB = Qb + (uint32_t)(lane & 15) * QSP + (lane >> 4) * 16;
#pragma unroll
        for (int ks = 0; ks < 4; ks++) {
            ldsm4(qa[0][ks], aB + 0 * 2304 + ks * 32);
            ldsm4(qa[1][ks], aB + 1 * 2304 + ks * 32);
            ldsm4(qa[2][ks], aB + 2 * 2304 + ks * 32);
        }
    }

    // ---- Phase 2b: scores via 8-term MMA, 128-col tiles ----
    {
        const int wn = warp * 16;
        const uint32_t bB = Ub + (uint32_t)(wn + ((lane >> 4) << 3) + (lane & 7)) * QSP
                               + ((lane >> 3) & 1) * 16;
        const int nt2 = (n_max + 127) >> 7;

        for (int t = 0; t < nt2; t++) {
            const int c0 = t << 7;
            __syncthreads();   // protects prior tile reads (and initial Q ldsm)
#pragma unroll
            for (int s = 0; s < 4; s++) {
                int idx = s * 256 + tid;
                int r = idx >> 3, seg = idx & 7;
                size_t g = (size_t)(c0 + r) * DIM + hh * HD + seg * 8;
                cp16(Ub + OFF_KH + r * QSP + seg * 16, Kh + g);
                cp16(Ub + OFF_KM + r * QSP + seg * 16, Km + g);
                cp16(Ub + OFF_KL + r * QSP + seg * 16, Kl + g);
            }
            asm volatile("cp.async.commit_group;");
            asm volatile("cp.async.wait_group 0;");
            __syncthreads();

            float acc[2][4];
#pragma unroll
            for (int nb = 0; nb < 2; nb++)
#pragma unroll
                for (int q = 0; q < 4; q++) acc[nb][q] = 0.f;

#pragma unroll
            for (int ks = 0; ks < 4; ks++) {
                uint32_t bh[4], bm[4], bl[4];
                ldsm4(bh, bB + OFF_KH + ks * 32);
                ldsm4(bm, bB + OFF_KM + ks * 32);
                ldsm4(bl, bB + OFF_KL + ks * 32);
                // 8 terms: hh, mh, hm, mm, hl, lh, ml, lm
                mma16816(acc[0], qa[0][ks], &bh[0]); mma16816(acc[1], qa[0][ks], &bh[2]);
                mma16816(acc[0], qa[1][ks], &bh[0]); mma16816(acc[1], qa[1][ks], &bh[2]);
                mma16816(acc[0], qa[0][ks], &bm[0]); mma16816(acc[1], qa[0][ks], &bm[2]);
                mma16816(acc[0], qa[1][ks], &bm[0]); mma16816(acc[1], qa[1][ks], &bm[2]);
                mma16816(acc[0], qa[0][ks], &bl[0]); mma16816(acc[1], qa[0][ks], &bl[2]);
                mma16816(acc[0], qa[2][ks], &bh[0]); mma16816(acc[1], qa[2][ks], &bh[2]);
                mma16816(acc[0], qa[1][ks], &bl[0]); mma16816(acc[1], qa[1][ks], &bl[2]);
                mma16816(acc[0], qa[2][ks], &bm[0]); mma16816(acc[1], qa[2][ks], &bm[2]);
            }

            const int g = lane >> 2, t2 = (lane & 3) * 2;
#pragma unroll
            for (int nb = 0; nb < 2; nb++) {
                const int col = c0 + wn + nb * 8 + t2;
                *(float2*)&sc[(size_t)g * SCP + col] =
                    make_float2(acc[nb][0], acc[nb][1]);
                *(float2*)&sc[(size_t)(g + 8) * SCP + col] =
                    make_float2(acc[nb][2], acc[nb][3]);
            }
        }
    }
    __syncthreads();

    // ---- Phase 3: entmax per row (warp Michelot, float4-vectorized) ----
    {
        const int w = warp;
        const int tile_end = (n_max + 255) & ~255;   // phase-4 256-tile extent
        for (int rr = w; rr < ROWS; rr += 8) {
            const int n = r0 + rr + 1;
            float* srow = sc + (size_t)rr * SCP;
            const float4* srow4 = (const float4*)srow;
            const int nv = n >> 2;
            const int ntail = nv << 2;

            float ssum = 0.f;
            for (int q = lane; q < nv; q += 32) {
                float4 v = srow4[q];
                ssum += (v.x + v.y) + (v.z + v.w);
            }
            for (int j = ntail + lane; j < n; j += 32) ssum += srow[j];
#pragma unroll
            for (int o = 16; o; o >>= 1) ssum += __shfl_xor_sync(0xFFFFFFFFu, ssum, o);

            int k = n;
            float tau = (ssum - 1.0f) / (float)n;
            for (int it = 0; it < SEQ; ++it) {
                float sa = 0.f; int ca = 0;
                for (int q = lane; q < nv; q += 32) {
                    float4 v = srow4[q];
                    if (v.x > tau) { sa += v.x; ca++; }
                    if (v.y > tau) { sa += v.y; ca++; }
                    if (v.z > tau) { sa += v.z; ca++; }
                    if (v.w > tau) { sa += v.w; ca++; }
                }
                for (int j = ntail + lane; j < n; j += 32) {
                    float v = srow[j];
                    if (v > tau) { sa += v; ca++; }
                }
#pragma unroll
                for (int o = 16; o; o >>= 1) {
                    sa += __shfl_xor_sync(0xFFFFFFFFu, sa, o);
                    ca += __shfl_xor_sync(0xFFFFFFFFu, ca, o);
                }
                if (ca == k) break;
                k = ca;
                tau = (sa - 1.0f) / (float)ca;
            }

            const float tau_star = (ssum - 1.0f) / (float)k;  // reference quirk: TOTAL sum

            float psum = 0.f;
            for (int q = lane; q < nv; q += 32) {
                float4 v = srow4[q];
                psum += fmaxf(v.x - tau_star, 0.f) + fmaxf(v.y - tau_star, 0.f)
                      + fmaxf(v.z - tau_star, 0.f) + fmaxf(v.w - tau_star, 0.f);
            }
            for (int j = ntail + lane; j < n; j += 32)
                psum += fmaxf(srow[j] - tau_star, 0.f);
#pragma unroll
            for (int o = 16; o; o >>= 1) psum += __shfl_xor_sync(0xFFFFFFFFu, psum, o);
            const float inv = 1.0f / (psum + 1e-10f);

            float4* srow4w = (float4*)srow;
            for (int q = lane; q < nv; q += 32) {
                float4 v = srow4w[q];
                srow4w[q] = make_float4(fmaxf(v.x - tau_star, 0.f) * inv,
                                        fmaxf(v.y - tau_star, 0.f) * inv,
                                        fmaxf(v.z - tau_star, 0.f) * inv,
                                        fmaxf(v.w - tau_star, 0.f) * inv);
            }
            for (int j = ntail + lane; j < n; j += 32)
                srow[j] = fmaxf(srow[j] - tau_star, 0.f) * inv;
            for (int j = n + lane; j < tile_end; j += 32) srow[j] = 0.f;
        }
    }

    // ---- Phase 4: O = P.V, tensor cores (R14-proven) ----
    {
        const int kq = warp >> 2;
        const int wn = (warp & 3) * 16;
        const int ntiles = (n_max + COLT - 1) / COLT;

        const uint32_t aBase = Ub + OFF_PH + (uint32_t)(lane & 15) * VPITCH
                                          + (lane >> 4) * 16;
        const uint32_t bBase = Ub + OFF_VH
                             + (uint32_t)(wn + ((lane >> 4) << 3) + (lane & 7)) * VPITCH
                             + ((lane >> 3) & 1) * 16;

        float acc[2][4];
#pragma unroll
        for (int nb = 0; nb < 2; nb++)
#pragma unroll
            for (int q = 0; q < 4; q++) acc[nb][q] = 0.f;

        for (int t = 0; t < ntiles; t++) {
            const int c0 = t * COLT;
            __syncthreads();
            {
                const char* srcH = (const char*)(VTh + (size_t)hh * 64 * SEQ + c0);
                const char* srcM = (const char*)(VTm + (size_t)hh * 64 * SEQ + c0);
#pragma unroll
                for (int s = 0; s < 8; s++) {
                    int idx = s * 256 + tid;
                    int d = idx >> 5, seg = idx & 31;
                    cp16(Ub + OFF_VH + d * VPITCH + seg * 16,
                         srcH + (size_t)d * SEQ * 2 + seg * 16);
                    cp16(Ub + OFF_VM + d * VPITCH + seg * 16,
                         srcM + (size_t)d * SEQ * 2 + seg * 16);
                }
                asm volatile("cp.async.commit_group;");
            }
#pragma unroll
            for (int s = 0; s < 8; s++) {
                int p = s * 256 + tid;
                int r = p >> 7, jp = p & 127;
                float2 v = *(const float2*)&sc[(size_t)r * SCP + c0 + jp * 2];
                uint32_t hb = bf2h(v);
                uint32_t mb = bf2m(v, hb);
                *(uint32_t*)(Uc + OFF_PH + r * VPITCH + jp * 4) = hb;
                *(uint32_t*)(Uc + OFF_PM + r * VPITCH + jp * 4) = mb;
            }
            asm volatile("cp.async.wait_group 0;");
            __syncthreads();

#pragma unroll
            for (int ks = 0; ks < 8; ks++) {
                const uint32_t ko = kq * 256 + ks * 32;
                uint32_t ah[4], am[4], bh[4], bm[4];
                ldsm4(ah, aBase + ko);
                ldsm4(bh, bBase + ko);
                ldsm4(am, aBase + (OFF_PM - OFF_PH) + ko);
                ldsm4(bm, bBase + (OFF_VM - OFF_VH) + ko);
                mma16816(acc[0], ah, &bh[0]);
                mma16816(acc[1], ah, &bh[2]);
                mma16816(acc[0], am, &bh[0]);
                mma16816(acc[1], am, &bh[2]);
                mma16816(acc[0], ah, &bm[0]);
                mma16816(acc[1], ah, &bm[2]);
            }
        }

        __syncthreads();
        float* red = kv;
        const int g = lane >> 2, tt = lane & 3;
#pragma unroll
        for (int nb = 0; nb < 2; nb++) {
            const int col = wn + nb * 8 + tt * 2;
            red[kq * 1024 + g * 64 + col]           = acc[nb][0];
            red[kq * 1024 + g * 64 + col + 1]       = acc[nb][1];
            red[kq * 1024 + (g + 8) * 64 + col]     = acc[nb][2];
            red[kq * 1024 + (g + 8) * 64 + col + 1] = acc[nb][3];
        }
        __syncthreads();
        {
            const int m = tid >> 4, dq = tid & 15;
            float4 a = *(const float4*)&red[m * 64 + dq * 4];
            float4 b = *(const float4*)&red[1024 + m * 64 + dq * 4];
            float fv[4] = {a.x + b.x, a.y + b.y, a.z + b.z, a.w + b.w};
            __nv_bfloat16 bh[4], bm[4];
#pragma unroll
            for (int q = 0; q < 4; q++) {
                bh[q] = __float2bfloat16_rn(fv[q]);
                bm[q] = __float2bfloat16_rn(fv[q] - __bfloat162float(bh[q]));
            }
            size_t idx = (size_t)(r0 + m) * DIM + hh * HD + dq * 4;
            *(__nv_bfloat162*)&AOh[idx]     = __nv_bfloat162(bh[0], bh[1]);
            *(__nv_bfloat162*)&AOh[idx + 2] = __nv_bfloat162(bh[2], bh[3]);
            *(__nv_bfloat162*)&AOm[idx]     = __nv_bfloat162(bm[0], bm[1]);
            *(__nv_bfloat162*)&AOm[idx + 2] = __nv_bfloat162(bm[2], bm[3]);
        }
    }
}

// ---------------------------------------------------------------------------
extern "C" void kernel_launch(void* const* d_in, const int* in_sizes, int n_in,
                              void* d_out, int out_size)
{
    const float* x  = (const float*)d_in[0];
    const float* Wq = (const float*)d_in[1];
    const float* Wk = (const float*)d_in[2];
    const float* Wv = (const float*)d_in[3];
    const float* Wo = (const float*)d_in[4];
    float* out = (float*)d_out;

    __nv_bfloat16 *qh, *qm, *ql, *kh, *km, *kl;
    __nv_bfloat16 *vth, *vtm, *xh, *xm, *aoh, *aom, *wvh, *wvm, *woh, *wom;
    cudaGetSymbolAddress((void**)&qh,  g_qh);  cudaGetSymbolAddress((void**)&qm,  g_qm);
    cudaGetSymbolAddress((void**)&ql,  g_ql);
    cudaGetSymbolAddress((void**)&kh,  g_kh);  cudaGetSymbolAddress((void**)&km,  g_km);
    cudaGetSymbolAddress((void**)&kl,  g_kl);
    cudaGetSymbolAddress((void**)&vth, g_vth); cudaGetSymbolAddress((void**)&vtm, g_vtm);
    cudaGetSymbolAddress((void**)&xh,  g_xh);  cudaGetSymbolAddress((void**)&xm,  g_xm);
    cudaGetSymbolAddress((void**)&aoh, g_aoh); cudaGetSymbolAddress((void**)&aom, g_aom);
    cudaGetSymbolAddress((void**)&wvh, g_wvh); cudaGetSymbolAddress((void**)&wvm, g_wvm);
    cudaGetSymbolAddress((void**)&woh, g_woh); cudaGetSymbolAddress((void**)&wom, g_wom);

    const size_t attn_smem = (size_t)ROWS * SCP * 4 + 3 * 16 * QSP + UNION_BYTES;
    cudaFuncSetAttribute(attn_kernel, cudaFuncAttributeMaxDynamicSharedMemorySize,
                         (int)attn_smem);
    cudaFuncSetAttribute(gemm_bf3_t<false>, cudaFuncAttributeMaxDynamicSharedMemorySize, GSMEM);
    cudaFuncSetAttribute(gemm_bf3_t<true>,  cudaFuncAttributeMaxDynamicSharedMemorySize, GSMEM);

    const int n4x = SEQ * DIM / 4;
    const int n4w = DIM * DIM / 4;

    split2<<<n4x / 256, 256>>>(x,  xh,  xm,  n4x);
    split2<<<n4w / 256, 256>>>(Wv, wvh, wvm, n4w);
    split2<<<n4w / 256, 256>>>(Wo, woh, wom, n4w);

    {   // Q,K projections: fp32-faithful accumulation, h/m/l split epilogue
        dim3 grid(DIM / 128, SEQ / 128, 2);
        sgemm_split<<<grid, 256>>>(x, Wq, Wk, qh, qm, ql, kh, km, kl, DIM, DIM);
    }
    {   // V projection: bf16x3 tensor cores, writes transposed bf16 h/m
        dim3 grid(DIM / 128, SEQ / 128, 1);
        gemm_bf3_t<true><<<grid, 256, GSMEM>>>(xh, xm, wvh, wvm,
                                               nullptr, vth, vtm, DIM, DIM);
    }
    {   // fused entmax attention (tensor-core scores + PV)
        dim3 grid(SEQ / ROWS, NH);
        attn_kernel<<<grid, 256, attn_smem>>>(qh, qm, ql, kh, km, kl,
                                              vth, vtm, aoh, aom);
    }
    {   // output projection: bf16x3 tensor cores
        dim3 grid(DIM / 128, SEQ / 128, 1);
        gemm_bf3_t<false><<<grid, 256, GSMEM>>>(aoh, aom, woh, wom,
                                                out, nullptr, nullptr, DIM, DIM);
    }
}